// round 1
// baseline (speedup 1.0000x reference)
#include <cuda_runtime.h>
#include <math.h>

#define NN 100000
#define NE 1600000

// ---------------- scratch (device globals: no allocation allowed) -------------
__device__ float g_u[NN * 64];     // u = (H @ W) * dis   (pre-aggregation, scaled)
__device__ float g_h[NN * 64];     // layer output after aggregate+bias+relu
__device__ float g_dis[NN];        // D^{-1/2}
__device__ float g_u3[NN];         // layer-3 scalar pre-aggregation
__device__ int   g_cnt[NN];        // in-degree (without self loop)
__device__ int   g_cur[NN];        // fill cursors
__device__ int   g_off[NN + 1];    // CSR offsets
__device__ int   g_part[256];      // scan partials
__device__ int   g_partx[256];     // scan partials (exclusive)
__device__ int   g_csr[NE];        // src per dst-sorted slot
__device__ int   g_is64;           // edge_index element width flag

// ---------------- edge dtype detection ---------------------------------------
__global__ void detect_dtype(const int* ei32) {
    // If data is int64 (values < 2^31), every odd 32-bit word of the first 256
    // entries is 0. If int32, those words are random node ids (~never all 0).
    int bad = (ei32[2 * threadIdx.x + 1] != 0) ? 1 : 0;
    int any = __syncthreads_or(bad);
    if (threadIdx.x == 0) g_is64 = any ? 0 : 1;
}

__device__ __forceinline__ void load_edge(const void* ei, int e, int is64, int& s, int& d) {
    if (is64) {
        const long long* p = (const long long*)ei;
        s = (int)p[e];
        d = (int)p[NE + e];
    } else {
        const int* p = (const int*)ei;
        s = p[e];
        d = p[NE + e];
    }
}

// ---------------- CSR build ---------------------------------------------------
__global__ void zero_k() {
    int i = blockIdx.x * blockDim.x + threadIdx.x;
    if (i < NN) { g_cnt[i] = 0; g_cur[i] = 0; }
}

__global__ void count_k(const void* ei) {
    int e = blockIdx.x * blockDim.x + threadIdx.x;
    if (e < NE) {
        int s, d;
        load_edge(ei, e, g_is64, s, d);
        atomicAdd(&g_cnt[d], 1);
    }
}

// inclusive scan of g_cnt into g_off[i+1], block partials to g_part
__global__ void scan1() {
    __shared__ int sd[512];
    int t = threadIdx.x;
    int i = blockIdx.x * 512 + t;
    int v = (i < NN) ? g_cnt[i] : 0;
    sd[t] = v;
    __syncthreads();
    #pragma unroll
    for (int d = 1; d < 512; d <<= 1) {
        int x = (t >= d) ? sd[t - d] : 0;
        __syncthreads();
        sd[t] += x;
        __syncthreads();
    }
    if (i < NN) g_off[i + 1] = sd[t];
    if (t == 511) g_part[blockIdx.x] = sd[511];
}

#define SCAN_NBLK 196  // ceil(100000/512)

__global__ void scan2() {
    __shared__ int sd[256];
    int t = threadIdx.x;
    int v = (t < SCAN_NBLK) ? g_part[t] : 0;
    sd[t] = v;
    __syncthreads();
    #pragma unroll
    for (int d = 1; d < 256; d <<= 1) {
        int x = (t >= d) ? sd[t - d] : 0;
        __syncthreads();
        sd[t] += x;
        __syncthreads();
    }
    if (t < SCAN_NBLK) g_partx[t] = sd[t] - v;  // exclusive
}

__global__ void scan3() {
    int i = blockIdx.x * blockDim.x + threadIdx.x;
    if (i < NN) {
        g_off[i + 1] += g_partx[i >> 9];
        g_dis[i] = rsqrtf((float)g_cnt[i] + 1.0f);  // +1 for self loop; deg>=1 always
        if (i == 0) g_off[0] = 0;
    }
}

__global__ void fill_k(const void* ei) {
    int e = blockIdx.x * blockDim.x + threadIdx.x;
    if (e < NE) {
        int s, d;
        load_edge(ei, e, g_is64, s, d);
        int pos = g_off[d] + atomicAdd(&g_cur[d], 1);
        g_csr[pos] = s;
    }
}

// ---------------- GEMM: g_u[row] = (A[row] @ W) * dis[row] --------------------
// 64 rows x 64 cols per block, 256 threads, 4x4 micro-tile.
// K staged in chunks of 64 -> 32KB static smem, XOR-swizzled A tile.
template <int K, bool FROM_H>
__global__ void gemm_scaled(const float* __restrict__ Ain, const float* __restrict__ W) {
    __shared__ float4 As4[64 * 16];
    __shared__ float4 Ws4[64 * 16];

    const float* A = FROM_H ? g_h : Ain;
    const int tid  = threadIdx.x;
    const int row0 = blockIdx.x * 64;
    const int tx = tid & 15, ty = tid >> 4;
    constexpr int C4full = K / 4;

    float acc[4][4] = {};

    for (int kk = 0; kk < K; kk += 64) {
        // stage A tile (swizzled) and W tile
        const float4* Ag = (const float4*)A;
        #pragma unroll
        for (int idx = tid; idx < 64 * 16; idx += 256) {
            int r = idx >> 4, c4 = idx & 15;
            float4 v = make_float4(0.f, 0.f, 0.f, 0.f);
            int row = row0 + r;
            if (row < NN) v = Ag[(size_t)row * C4full + (kk >> 2) + c4];
            As4[(r << 4) + (c4 ^ (r & 15))] = v;
        }
        const float4* Wg = (const float4*)W;
        #pragma unroll
        for (int idx = tid; idx < 64 * 16; idx += 256) {
            int kloc = idx >> 4, c4 = idx & 15;
            Ws4[idx] = Wg[(size_t)(kk + kloc) * 16 + c4];
        }
        __syncthreads();

        const float* As = (const float*)As4;
        #pragma unroll 8
        for (int k = 0; k < 64; k++) {
            int k4 = k >> 2, kr = k & 3;
            float4 w = Ws4[(k << 4) + tx];
            #pragma unroll
            for (int j = 0; j < 4; j++) {
                int r = (ty << 2) + j;
                float a = As[(((r << 4) + (k4 ^ (r & 15))) << 2) + kr];
                acc[j][0] += a * w.x;
                acc[j][1] += a * w.y;
                acc[j][2] += a * w.z;
                acc[j][3] += a * w.w;
            }
        }
        __syncthreads();
    }

    #pragma unroll
    for (int j = 0; j < 4; j++) {
        int row = row0 + (ty << 2) + j;
        if (row < NN) {
            float s = g_dis[row];
            float4 o = make_float4(acc[j][0] * s, acc[j][1] * s, acc[j][2] * s, acc[j][3] * s);
            ((float4*)g_u)[(size_t)row * 16 + tx] = o;
        }
    }
}

// ---------------- aggregate + bias + relu ------------------------------------
// h[d] = relu( dis[d] * ( sum_{e->d} u[src] + u[d] ) + b )
// 16 lanes per node, each lane owns a float4 (4 of 64 cols). 16 nodes/block.
__global__ void agg_relu(const float* __restrict__ b) {
    int tid = threadIdx.x;
    int grp = tid >> 4, sub = tid & 15;
    int d = blockIdx.x * 16 + grp;  // 6250 blocks * 16 = 100000 exact

    const float4* U4 = (const float4*)g_u;
    float4 acc = U4[(size_t)d * 16 + sub];  // self-loop term
    int e = g_off[d], end = g_off[d + 1];
    #pragma unroll 4
    for (; e < end; e++) {
        int s = g_csr[e];
        float4 v = U4[(size_t)s * 16 + sub];
        acc.x += v.x; acc.y += v.y; acc.z += v.z; acc.w += v.w;
    }
    float sc = g_dis[d];
    float4 bb = ((const float4*)b)[sub];
    float4 o;
    o.x = fmaxf(sc * acc.x + bb.x, 0.f);
    o.y = fmaxf(sc * acc.y + bb.y, 0.f);
    o.z = fmaxf(sc * acc.z + bb.z, 0.f);
    o.w = fmaxf(sc * acc.w + bb.w, 0.f);
    ((float4*)g_h)[(size_t)d * 16 + sub] = o;
}

// ---------------- layer 3: u3[i] = dot(h[i], W3) * dis[i] ---------------------
__global__ void dot3_k(const float* __restrict__ W3) {
    int lane = threadIdx.x & 31, w = threadIdx.x >> 5;
    int d = blockIdx.x * 8 + w;  // 12500 blocks * 8 = 100000 exact
    float v = g_h[(size_t)d * 64 + lane] * W3[lane] +
              g_h[(size_t)d * 64 + lane + 32] * W3[lane + 32];
    #pragma unroll
    for (int o = 16; o; o >>= 1) v += __shfl_xor_sync(0xffffffffu, v, o);
    if (lane == 0) g_u3[d] = v * g_dis[d];
}

// ---------------- final: out = sigmoid(dis*(sum u3 + u3[d]) + b3) -------------
__global__ void final_k(const float* __restrict__ b3, float* __restrict__ out) {
    int d = blockIdx.x * blockDim.x + threadIdx.x;
    if (d < NN) {
        float s = g_u3[d];
        int e = g_off[d], end = g_off[d + 1];
        #pragma unroll 4
        for (; e < end; e++) s += g_u3[g_csr[e]];
        float z = g_dis[d] * s + b3[0];
        out[d] = 1.0f / (1.0f + expf(-z));
    }
}

// ---------------- launch -------------------------------------------------------
extern "C" void kernel_launch(void* const* d_in, const int* in_sizes, int n_in,
                              void* d_out, int out_size) {
    const float* x  = (const float*)d_in[0];
    const float* W1 = (const float*)d_in[1];
    const float* b1 = (const float*)d_in[2];
    const float* W2 = (const float*)d_in[3];
    const float* b2 = (const float*)d_in[4];
    const float* W3 = (const float*)d_in[5];
    const float* b3 = (const float*)d_in[6];
    const void*  ei = d_in[7];
    float* out = (float*)d_out;

    // graph structure (shared by all layers)
    detect_dtype<<<1, 256>>>((const int*)ei);
    zero_k<<<(NN + 255) / 256, 256>>>();
    count_k<<<(NE + 255) / 256, 256>>>(ei);
    scan1<<<SCAN_NBLK, 512>>>();
    scan2<<<1, 256>>>();
    scan3<<<(NN + 255) / 256, 256>>>();
    fill_k<<<(NE + 255) / 256, 256>>>(ei);

    // layer 1
    gemm_scaled<128, false><<<(NN + 63) / 64, 256>>>(x, W1);
    agg_relu<<<NN / 16, 256>>>(b1);
    // layer 2
    gemm_scaled<64, true><<<(NN + 63) / 64, 256>>>(nullptr, W2);
    agg_relu<<<NN / 16, 256>>>(b2);
    // layer 3
    dot3_k<<<NN / 8, 256>>>(W3);
    final_k<<<(NN + 255) / 256, 256>>>(b3, out);
}

// round 3
// speedup vs baseline: 1.2782x; 1.2782x over previous
#include <cuda_runtime.h>
#include <cuda_bf16.h>
#include <math.h>
#include <stdint.h>

#define NN 100000
#define NE 1600000

// ---------------- scratch (device globals: no allocation allowed) -------------
__device__ float g_u[NN * 64];     // u = (H @ W) * dis   (pre-aggregation, scaled)
__device__ float g_h[NN * 64];     // layer output after aggregate+bias+relu
__device__ float g_dis[NN];        // D^{-1/2}
__device__ float g_u3[NN];         // layer-3 scalar pre-aggregation
__device__ int   g_cnt[NN];        // in-degree (without self loop)
__device__ int   g_cur[NN];        // fill cursors
__device__ int   g_off[NN + 1];    // CSR offsets
__device__ int   g_part[256];      // scan partials
__device__ int   g_partx[256];     // scan partials (exclusive)
__device__ int   g_csr[NE];        // src per dst-sorted slot
__device__ int   g_is64;           // edge_index element width flag

// ---------------- helpers ------------------------------------------------------
__device__ __forceinline__ uint32_t smem_u32(const void* p) {
    uint32_t a;
    asm("{ .reg .u64 t; cvta.to.shared.u64 t, %1; cvt.u32.u64 %0, t; }" : "=r"(a) : "l"(p));
    return a;
}
#define SWZ128(o) ((o) ^ (((o) >> 3) & 0x70))

__device__ __forceinline__ void ldsm_x4(uint32_t a, uint32_t& r0, uint32_t& r1,
                                        uint32_t& r2, uint32_t& r3) {
    asm volatile("ldmatrix.sync.aligned.m8n8.x4.shared.b16 {%0,%1,%2,%3}, [%4];"
                 : "=r"(r0), "=r"(r1), "=r"(r2), "=r"(r3) : "r"(a));
}
__device__ __forceinline__ void mma_bf16(float* d, const uint32_t* a, uint32_t b0, uint32_t b1) {
    asm volatile("mma.sync.aligned.m16n8k16.row.col.f32.bf16.bf16.f32 "
                 "{%0,%1,%2,%3}, {%4,%5,%6,%7}, {%8,%9}, {%0,%1,%2,%3};"
                 : "+f"(d[0]), "+f"(d[1]), "+f"(d[2]), "+f"(d[3])
                 : "r"(a[0]), "r"(a[1]), "r"(a[2]), "r"(a[3]), "r"(b0), "r"(b1));
}

// ---------------- edge dtype detection ---------------------------------------
__global__ void detect_dtype(const int* ei32) {
    int bad = (ei32[2 * threadIdx.x + 1] != 0) ? 1 : 0;
    int any = __syncthreads_or(bad);
    if (threadIdx.x == 0) g_is64 = any ? 0 : 1;
}

__device__ __forceinline__ void load_edge(const void* ei, int e, int is64, int& s, int& d) {
    if (is64) {
        const long long* p = (const long long*)ei;
        s = (int)p[e];
        d = (int)p[NE + e];
    } else {
        const int* p = (const int*)ei;
        s = p[e];
        d = p[NE + e];
    }
}

// ---------------- CSR build ---------------------------------------------------
__global__ void zero_k() {
    int i = blockIdx.x * blockDim.x + threadIdx.x;
    if (i < NN) { g_cnt[i] = 0; g_cur[i] = 0; }
}

__global__ void count_k(const void* ei) {
    int e = blockIdx.x * blockDim.x + threadIdx.x;
    if (e < NE) {
        int s, d;
        load_edge(ei, e, g_is64, s, d);
        atomicAdd(&g_cnt[d], 1);
    }
}

__global__ void scan1() {
    __shared__ int sd[512];
    int t = threadIdx.x;
    int i = blockIdx.x * 512 + t;
    int v = (i < NN) ? g_cnt[i] : 0;
    sd[t] = v;
    __syncthreads();
    #pragma unroll
    for (int d = 1; d < 512; d <<= 1) {
        int x = (t >= d) ? sd[t - d] : 0;
        __syncthreads();
        sd[t] += x;
        __syncthreads();
    }
    if (i < NN) g_off[i + 1] = sd[t];
    if (t == 511) g_part[blockIdx.x] = sd[511];
}

#define SCAN_NBLK 196  // ceil(100000/512)

__global__ void scan2() {
    __shared__ int sd[256];
    int t = threadIdx.x;
    int v = (t < SCAN_NBLK) ? g_part[t] : 0;
    sd[t] = v;
    __syncthreads();
    #pragma unroll
    for (int d = 1; d < 256; d <<= 1) {
        int x = (t >= d) ? sd[t - d] : 0;
        __syncthreads();
        sd[t] += x;
        __syncthreads();
    }
    if (t < SCAN_NBLK) g_partx[t] = sd[t] - v;  // exclusive
}

__global__ void scan3() {
    int i = blockIdx.x * blockDim.x + threadIdx.x;
    if (i < NN) {
        g_off[i + 1] += g_partx[i >> 9];
        g_dis[i] = rsqrtf((float)g_cnt[i] + 1.0f);
        if (i == 0) g_off[0] = 0;
    }
}

__global__ void fill_k(const void* ei) {
    int e = blockIdx.x * blockDim.x + threadIdx.x;
    if (e < NE) {
        int s, d;
        load_edge(ei, e, g_is64, s, d);
        int pos = g_off[d] + atomicAdd(&g_cur[d], 1);
        g_csr[pos] = s;
    }
}

// ---------------- MMA split-bf16 GEMM ------------------------------------------
// g_u[row, 0:64] = (A[row, 0:K] @ W[K, 64]) * dis[row]
// 256 rows/CTA, 8 warps x 32 rows. K staged in 64-chunks, SW128-swizzled smem.
// D = AhWh + AhWl + AlWh (fp32 acc), dropped AlWl term ~1.6e-5 relative.
template <int KCHUNKS, bool FROM_H>
__global__ void __launch_bounds__(256)
gemm_mma(const float* __restrict__ Ain, const float* __restrict__ W) {
    extern __shared__ char dsm[];
    uint32_t sb0 = smem_u32(dsm);
    uint32_t sb = (sb0 + 1023) & ~1023u;
    char* p = dsm + (sb - sb0);
    // layout (per 64-wide k-chunk): Ah[256x64bf16]=32KB, Al=32KB, Bh[64x64bf16]=8KB, Bl=8KB
    const uint32_t AH = sb, AL = sb + 32768, BH = sb + 65536, BL = sb + 73728;
    char* pAH = p;
    char* pAL = p + 32768;
    char* pBH = p + 65536;
    char* pBL = p + 73728;

    const float* A = FROM_H ? g_h : Ain;
    constexpr int K = KCHUNKS * 64;
    const int tid = threadIdx.x, wid = tid >> 5, lane = tid & 31;
    const int row0 = blockIdx.x * 256;
    const int g = lane >> 2, tig = lane & 3;

    float acc[2][8][4];
    #pragma unroll
    for (int i = 0; i < 2; i++)
        #pragma unroll
        for (int j = 0; j < 8; j++)
            #pragma unroll
            for (int r = 0; r < 4; r++) acc[i][j][r] = 0.f;

    for (int ch = 0; ch < KCHUNKS; ch++) {
        __syncthreads();  // previous chunk's mma reads done before restage

        // ---- stage A chunk: 256 rows x 64 cols fp32 -> bf16 hi/lo swizzled ----
        #pragma unroll
        for (int it = tid; it < 4096; it += 256) {   // 256 rows * 16 float4
            int r = it >> 4, c4 = it & 15;
            int row = row0 + r;
            float4 v = make_float4(0.f, 0.f, 0.f, 0.f);
            if (row < NN) v = ((const float4*)A)[(size_t)row * (K / 4) + ch * 16 + c4];
            __nv_bfloat16 hx = __float2bfloat16_rn(v.x);
            __nv_bfloat16 hy = __float2bfloat16_rn(v.y);
            __nv_bfloat16 hz = __float2bfloat16_rn(v.z);
            __nv_bfloat16 hw = __float2bfloat16_rn(v.w);
            __nv_bfloat16 lx = __float2bfloat16_rn(v.x - __bfloat162float(hx));
            __nv_bfloat16 ly = __float2bfloat16_rn(v.y - __bfloat162float(hy));
            __nv_bfloat16 lz = __float2bfloat16_rn(v.z - __bfloat162float(hz));
            __nv_bfloat16 lw = __float2bfloat16_rn(v.w - __bfloat162float(hw));
            uint32_t so = SWZ128((uint32_t)(r * 128 + c4 * 8));
            __nv_bfloat162 h01(hx, hy), h23(hz, hw), l01(lx, ly), l23(lz, lw);
            uint2 hv = make_uint2(*(uint32_t*)&h01, *(uint32_t*)&h23);
            uint2 lv = make_uint2(*(uint32_t*)&l01, *(uint32_t*)&l23);
            *(uint2*)(pAH + so) = hv;
            *(uint2*)(pAL + so) = lv;
        }
        // ---- stage B chunk: Wt[n][k] from W[k][n], bf16 hi/lo swizzled ----
        #pragma unroll
        for (int it = tid; it < 4096; it += 256) {   // 64 k * 64 n
            int kloc = it >> 6, n = it & 63;
            float w = W[(size_t)(ch * 64 + kloc) * 64 + n];
            __nv_bfloat16 hw_ = __float2bfloat16_rn(w);
            __nv_bfloat16 lw_ = __float2bfloat16_rn(w - __bfloat162float(hw_));
            uint32_t so = SWZ128((uint32_t)(n * 128 + kloc * 2));
            *(__nv_bfloat16*)(pBH + so) = hw_;
            *(__nv_bfloat16*)(pBL + so) = lw_;
        }
        __syncthreads();

        // ---- mma over 4 k-steps of 16 ----
        #pragma unroll
        for (int ks = 0; ks < 4; ks++) {
            uint32_t ar   = (uint32_t)(wid * 32 + (lane & 15));
            uint32_t akb  = (uint32_t)(ks * 32 + ((lane >> 4) << 4));
            uint32_t aof0 = SWZ128(ar * 128 + akb);
            uint32_t aof1 = SWZ128((ar + 16) * 128 + akb);
            uint32_t ah0[4], ah1[4], al0[4], al1[4];
            ldsm_x4(AH + aof0, ah0[0], ah0[1], ah0[2], ah0[3]);
            ldsm_x4(AH + aof1, ah1[0], ah1[1], ah1[2], ah1[3]);
            ldsm_x4(AL + aof0, al0[0], al0[1], al0[2], al0[3]);
            ldsm_x4(AL + aof1, al1[0], al1[1], al1[2], al1[3]);

            uint32_t bkb = (uint32_t)(ks * 32 + (((lane >> 3) & 1) << 4));
            #pragma unroll
            for (int jj = 0; jj < 4; jj++) {
                uint32_t bn = (uint32_t)(jj * 16 + (lane & 7) + ((lane >> 4) << 3));
                uint32_t bof = SWZ128(bn * 128 + bkb);
                uint32_t bh[4], bl[4];
                ldsm_x4(BH + bof, bh[0], bh[1], bh[2], bh[3]);
                ldsm_x4(BL + bof, bl[0], bl[1], bl[2], bl[3]);
                // n-chunk 2*jj uses b regs {0,1}; chunk 2*jj+1 uses {2,3}
                mma_bf16(acc[0][2 * jj], ah0, bh[0], bh[1]);
                mma_bf16(acc[0][2 * jj], ah0, bl[0], bl[1]);
                mma_bf16(acc[0][2 * jj], al0, bh[0], bh[1]);
                mma_bf16(acc[1][2 * jj], ah1, bh[0], bh[1]);
                mma_bf16(acc[1][2 * jj], ah1, bl[0], bl[1]);
                mma_bf16(acc[1][2 * jj], al1, bh[0], bh[1]);
                mma_bf16(acc[0][2 * jj + 1], ah0, bh[2], bh[3]);
                mma_bf16(acc[0][2 * jj + 1], ah0, bl[2], bl[3]);
                mma_bf16(acc[0][2 * jj + 1], al0, bh[2], bh[3]);
                mma_bf16(acc[1][2 * jj + 1], ah1, bh[2], bh[3]);
                mma_bf16(acc[1][2 * jj + 1], ah1, bl[2], bl[3]);
                mma_bf16(acc[1][2 * jj + 1], al1, bh[2], bh[3]);
            }
        }
    }

    // ---- epilogue: scale by dis, store fp32 ----
    #pragma unroll
    for (int G = 0; G < 2; G++) {
        int r_lo = row0 + wid * 32 + G * 16 + g;
        int r_hi = r_lo + 8;
        float s_lo = (r_lo < NN) ? g_dis[r_lo] : 0.f;
        float s_hi = (r_hi < NN) ? g_dis[r_hi] : 0.f;
        #pragma unroll
        for (int j = 0; j < 8; j++) {
            int col = j * 8 + tig * 2;
            if (r_lo < NN) {
                float2 o = make_float2(acc[G][j][0] * s_lo, acc[G][j][1] * s_lo);
                *(float2*)&g_u[(size_t)r_lo * 64 + col] = o;
            }
            if (r_hi < NN) {
                float2 o = make_float2(acc[G][j][2] * s_hi, acc[G][j][3] * s_hi);
                *(float2*)&g_u[(size_t)r_hi * 64 + col] = o;
            }
        }
    }
}

// ---------------- aggregate + bias + relu ------------------------------------
__global__ void agg_relu(const float* __restrict__ b) {
    int tid = threadIdx.x;
    int grp = tid >> 4, sub = tid & 15;
    int d = blockIdx.x * 16 + grp;

    const float4* U4 = (const float4*)g_u;
    float4 acc = U4[(size_t)d * 16 + sub];  // self-loop term
    int e = g_off[d], end = g_off[d + 1];
    #pragma unroll 4
    for (; e < end; e++) {
        int s = g_csr[e];
        float4 v = U4[(size_t)s * 16 + sub];
        acc.x += v.x; acc.y += v.y; acc.z += v.z; acc.w += v.w;
    }
    float sc = g_dis[d];
    float4 bb = ((const float4*)b)[sub];
    float4 o;
    o.x = fmaxf(sc * acc.x + bb.x, 0.f);
    o.y = fmaxf(sc * acc.y + bb.y, 0.f);
    o.z = fmaxf(sc * acc.z + bb.z, 0.f);
    o.w = fmaxf(sc * acc.w + bb.w, 0.f);
    ((float4*)g_h)[(size_t)d * 16 + sub] = o;
}

// ---------------- layer 3: u3[i] = dot(h[i], W3) * dis[i] ---------------------
__global__ void dot3_k(const float* __restrict__ W3) {
    int lane = threadIdx.x & 31, w = threadIdx.x >> 5;
    int d = blockIdx.x * 8 + w;
    float v = g_h[(size_t)d * 64 + lane] * W3[lane] +
              g_h[(size_t)d * 64 + lane + 32] * W3[lane + 32];
    #pragma unroll
    for (int o = 16; o; o >>= 1) v += __shfl_xor_sync(0xffffffffu, v, o);
    if (lane == 0) g_u3[d] = v * g_dis[d];
}

// ---------------- final: out = sigmoid(dis*(sum u3 + u3[d]) + b3) -------------
__global__ void final_k(const float* __restrict__ b3, float* __restrict__ out) {
    int d = blockIdx.x * blockDim.x + threadIdx.x;
    if (d < NN) {
        float s = g_u3[d];
        int e = g_off[d], end = g_off[d + 1];
        #pragma unroll 4
        for (; e < end; e++) s += g_u3[g_csr[e]];
        float z = g_dis[d] * s + b3[0];
        out[d] = 1.0f / (1.0f + expf(-z));
    }
}

// ---------------- launch -------------------------------------------------------
extern "C" void kernel_launch(void* const* d_in, const int* in_sizes, int n_in,
                              void* d_out, int out_size) {
    const float* x  = (const float*)d_in[0];
    const float* W1 = (const float*)d_in[1];
    const float* b1 = (const float*)d_in[2];
    const float* W2 = (const float*)d_in[3];
    const float* b2 = (const float*)d_in[4];
    const float* W3 = (const float*)d_in[5];
    const float* b3 = (const float*)d_in[6];
    const void*  ei = d_in[7];
    float* out = (float*)d_out;

    const int SMEM = 1024 + 65536 + 16384;  // pad + A(hi/lo) + B(hi/lo) = 82944
    cudaFuncSetAttribute(gemm_mma<2, false>, cudaFuncAttributeMaxDynamicSharedMemorySize, SMEM);
    cudaFuncSetAttribute(gemm_mma<1, true>,  cudaFuncAttributeMaxDynamicSharedMemorySize, SMEM);

    // graph structure (shared by all layers)
    detect_dtype<<<1, 256>>>((const int*)ei);
    zero_k<<<(NN + 255) / 256, 256>>>();
    count_k<<<(NE + 255) / 256, 256>>>(ei);
    scan1<<<SCAN_NBLK, 512>>>();
    scan2<<<1, 256>>>();
    scan3<<<(NN + 255) / 256, 256>>>();
    fill_k<<<(NE + 255) / 256, 256>>>(ei);

    const int NBLK = (NN + 255) / 256;  // 391

    // layer 1
    gemm_mma<2, false><<<NBLK, 256, SMEM>>>(x, W1);
    agg_relu<<<NN / 16, 256>>>(b1);
    // layer 2
    gemm_mma<1, true><<<NBLK, 256, SMEM>>>(nullptr, W2);
    agg_relu<<<NN / 16, 256>>>(b2);
    // layer 3
    dot3_k<<<NN / 8, 256>>>(W3);
    final_k<<<(NN + 255) / 256, 256>>>(b3, out);
}

// round 4
// speedup vs baseline: 1.4124x; 1.1050x over previous
#include <cuda_runtime.h>
#include <cuda_bf16.h>
#include <cuda_fp16.h>
#include <math.h>
#include <stdint.h>

#define NN 100000
#define NE 1600000

// ---------------- scratch (device globals: no allocation allowed) -------------
__device__ __half g_uh[NN * 64];   // u = (H @ W) * dis, fp16 (pre-aggregation)
__device__ float g_h[NN * 64];     // layer-1 output after aggregate+bias+relu
__device__ float g_dis[NN];        // D^{-1/2}
__device__ float g_u3[NN];         // layer-3 scalar pre-aggregation
__device__ int   g_cnt[NN];        // in-degree (without self loop)
__device__ int   g_cur[NN];        // fill cursors
__device__ int   g_off[NN + 1];    // CSR offsets
__device__ int   g_part[256];      // scan partials
__device__ int   g_partx[256];     // scan partials (exclusive)
__device__ int   g_csr[NE];        // src per dst-sorted slot
__device__ int   g_is64;           // edge_index element width flag

// ---------------- helpers ------------------------------------------------------
__device__ __forceinline__ uint32_t smem_u32(const void* p) {
    uint32_t a;
    asm("{ .reg .u64 t; cvta.to.shared.u64 t, %1; cvt.u32.u64 %0, t; }" : "=r"(a) : "l"(p));
    return a;
}
#define SWZ128(o) ((o) ^ (((o) >> 3) & 0x70))

__device__ __forceinline__ void ldsm_x4(uint32_t a, uint32_t& r0, uint32_t& r1,
                                        uint32_t& r2, uint32_t& r3) {
    asm volatile("ldmatrix.sync.aligned.m8n8.x4.shared.b16 {%0,%1,%2,%3}, [%4];"
                 : "=r"(r0), "=r"(r1), "=r"(r2), "=r"(r3) : "r"(a));
}
__device__ __forceinline__ void mma_bf16(float* d, const uint32_t* a, uint32_t b0, uint32_t b1) {
    asm volatile("mma.sync.aligned.m16n8k16.row.col.f32.bf16.bf16.f32 "
                 "{%0,%1,%2,%3}, {%4,%5,%6,%7}, {%8,%9}, {%0,%1,%2,%3};"
                 : "+f"(d[0]), "+f"(d[1]), "+f"(d[2]), "+f"(d[3])
                 : "r"(a[0]), "r"(a[1]), "r"(a[2]), "r"(a[3]), "r"(b0), "r"(b1));
}

// ---------------- edge dtype detection ---------------------------------------
__global__ void detect_dtype(const int* ei32) {
    int bad = (ei32[2 * threadIdx.x + 1] != 0) ? 1 : 0;
    int any = __syncthreads_or(bad);
    if (threadIdx.x == 0) g_is64 = any ? 0 : 1;
}

__device__ __forceinline__ void load_edge(const void* ei, int e, int is64, int& s, int& d) {
    if (is64) {
        const long long* p = (const long long*)ei;
        s = (int)p[e];
        d = (int)p[NE + e];
    } else {
        const int* p = (const int*)ei;
        s = p[e];
        d = p[NE + e];
    }
}

// ---------------- CSR build ---------------------------------------------------
__global__ void zero_k() {
    int i = blockIdx.x * blockDim.x + threadIdx.x;
    if (i < NN) { g_cnt[i] = 0; g_cur[i] = 0; }
}

__global__ void count_k(const void* ei) {
    int e = blockIdx.x * blockDim.x + threadIdx.x;
    if (e < NE) {
        int s, d;
        load_edge(ei, e, g_is64, s, d);
        atomicAdd(&g_cnt[d], 1);
    }
}

// warp-shuffle inclusive scan, 512/block
__global__ void scan1() {
    __shared__ int sw[16];
    int t = threadIdx.x, lane = t & 31, w = t >> 5;
    int i = blockIdx.x * 512 + t;
    int v = (i < NN) ? g_cnt[i] : 0;
    int x = v;
    #pragma unroll
    for (int o = 1; o < 32; o <<= 1) {
        int y = __shfl_up_sync(0xffffffffu, x, o);
        if (lane >= o) x += y;
    }
    if (lane == 31) sw[w] = x;
    __syncthreads();
    if (w == 0) {
        int s = (lane < 16) ? sw[lane] : 0;
        #pragma unroll
        for (int o = 1; o < 16; o <<= 1) {
            int y = __shfl_up_sync(0xffffffffu, s, o);
            if (lane >= o) s += y;
        }
        if (lane < 16) sw[lane] = s;
    }
    __syncthreads();
    if (w) x += sw[w - 1];
    if (i < NN) g_off[i + 1] = x;
    if (t == 511) g_part[blockIdx.x] = x;
}

#define SCAN_NBLK 196  // ceil(100000/512)

__global__ void scan2() {
    __shared__ int sd[256];
    int t = threadIdx.x;
    int v = (t < SCAN_NBLK) ? g_part[t] : 0;
    sd[t] = v;
    __syncthreads();
    #pragma unroll
    for (int d = 1; d < 256; d <<= 1) {
        int x = (t >= d) ? sd[t - d] : 0;
        __syncthreads();
        sd[t] += x;
        __syncthreads();
    }
    if (t < SCAN_NBLK) g_partx[t] = sd[t] - v;  // exclusive
}

__global__ void scan3() {
    int i = blockIdx.x * blockDim.x + threadIdx.x;
    if (i < NN) {
        g_off[i + 1] += g_partx[i >> 9];
        g_dis[i] = rsqrtf((float)g_cnt[i] + 1.0f);
        if (i == 0) g_off[0] = 0;
    }
}

__global__ void fill_k(const void* ei) {
    int e = blockIdx.x * blockDim.x + threadIdx.x;
    if (e < NE) {
        int s, d;
        load_edge(ei, e, g_is64, s, d);
        int pos = g_off[d] + atomicAdd(&g_cur[d], 1);
        g_csr[pos] = s;
    }
}

// ---------------- MMA split-bf16 GEMM ------------------------------------------
// g_uh[row, 0:64] = fp16( (A[row, 0:K] @ W[K, 64]) * dis[row] )
// 256 rows/CTA, 8 warps x 32 rows. K staged in 64-chunks, SW128-swizzled smem.
// D = AhWh + AhWl + AlWh (fp32 acc).
template <int KCHUNKS, bool FROM_H>
__global__ void __launch_bounds__(256)
gemm_mma(const float* __restrict__ Ain, const float* __restrict__ W) {
    extern __shared__ char dsm[];
    uint32_t sb0 = smem_u32(dsm);
    uint32_t sb = (sb0 + 1023) & ~1023u;
    char* p = dsm + (sb - sb0);
    const uint32_t AH = sb, AL = sb + 32768, BH = sb + 65536, BL = sb + 73728;
    char* pAH = p;
    char* pAL = p + 32768;
    char* pBH = p + 65536;
    char* pBL = p + 73728;

    const float* A = FROM_H ? g_h : Ain;
    constexpr int K = KCHUNKS * 64;
    const int tid = threadIdx.x, wid = tid >> 5, lane = tid & 31;
    const int row0 = blockIdx.x * 256;
    const int g = lane >> 2, tig = lane & 3;

    float acc[2][8][4];
    #pragma unroll
    for (int i = 0; i < 2; i++)
        #pragma unroll
        for (int j = 0; j < 8; j++)
            #pragma unroll
            for (int r = 0; r < 4; r++) acc[i][j][r] = 0.f;

    for (int ch = 0; ch < KCHUNKS; ch++) {
        __syncthreads();

        #pragma unroll
        for (int it = tid; it < 4096; it += 256) {   // 256 rows * 16 float4
            int r = it >> 4, c4 = it & 15;
            int row = row0 + r;
            float4 v = make_float4(0.f, 0.f, 0.f, 0.f);
            if (row < NN) v = ((const float4*)A)[(size_t)row * (K / 4) + ch * 16 + c4];
            __nv_bfloat16 hx = __float2bfloat16_rn(v.x);
            __nv_bfloat16 hy = __float2bfloat16_rn(v.y);
            __nv_bfloat16 hz = __float2bfloat16_rn(v.z);
            __nv_bfloat16 hw = __float2bfloat16_rn(v.w);
            __nv_bfloat16 lx = __float2bfloat16_rn(v.x - __bfloat162float(hx));
            __nv_bfloat16 ly = __float2bfloat16_rn(v.y - __bfloat162float(hy));
            __nv_bfloat16 lz = __float2bfloat16_rn(v.z - __bfloat162float(hz));
            __nv_bfloat16 lw = __float2bfloat16_rn(v.w - __bfloat162float(hw));
            uint32_t so = SWZ128((uint32_t)(r * 128 + c4 * 8));
            __nv_bfloat162 h01(hx, hy), h23(hz, hw), l01(lx, ly), l23(lz, lw);
            uint2 hv = make_uint2(*(uint32_t*)&h01, *(uint32_t*)&h23);
            uint2 lv = make_uint2(*(uint32_t*)&l01, *(uint32_t*)&l23);
            *(uint2*)(pAH + so) = hv;
            *(uint2*)(pAL + so) = lv;
        }
        #pragma unroll
        for (int it = tid; it < 4096; it += 256) {   // 64 k * 64 n
            int kloc = it >> 6, n = it & 63;
            float w = W[(size_t)(ch * 64 + kloc) * 64 + n];
            __nv_bfloat16 hw_ = __float2bfloat16_rn(w);
            __nv_bfloat16 lw_ = __float2bfloat16_rn(w - __bfloat162float(hw_));
            uint32_t so = SWZ128((uint32_t)(n * 128 + kloc * 2));
            *(__nv_bfloat16*)(pBH + so) = hw_;
            *(__nv_bfloat16*)(pBL + so) = lw_;
        }
        __syncthreads();

        #pragma unroll
        for (int ks = 0; ks < 4; ks++) {
            uint32_t ar   = (uint32_t)(wid * 32 + (lane & 15));
            uint32_t akb  = (uint32_t)(ks * 32 + ((lane >> 4) << 4));
            uint32_t aof0 = SWZ128(ar * 128 + akb);
            uint32_t aof1 = SWZ128((ar + 16) * 128 + akb);
            uint32_t ah0[4], ah1[4], al0[4], al1[4];
            ldsm_x4(AH + aof0, ah0[0], ah0[1], ah0[2], ah0[3]);
            ldsm_x4(AH + aof1, ah1[0], ah1[1], ah1[2], ah1[3]);
            ldsm_x4(AL + aof0, al0[0], al0[1], al0[2], al0[3]);
            ldsm_x4(AL + aof1, al1[0], al1[1], al1[2], al1[3]);

            uint32_t bkb = (uint32_t)(ks * 32 + (((lane >> 3) & 1) << 4));
            #pragma unroll
            for (int jj = 0; jj < 4; jj++) {
                uint32_t bn = (uint32_t)(jj * 16 + (lane & 7) + ((lane >> 4) << 3));
                uint32_t bof = SWZ128(bn * 128 + bkb);
                uint32_t bh[4], bl[4];
                ldsm_x4(BH + bof, bh[0], bh[1], bh[2], bh[3]);
                ldsm_x4(BL + bof, bl[0], bl[1], bl[2], bl[3]);
                mma_bf16(acc[0][2 * jj], ah0, bh[0], bh[1]);
                mma_bf16(acc[0][2 * jj], ah0, bl[0], bl[1]);
                mma_bf16(acc[0][2 * jj], al0, bh[0], bh[1]);
                mma_bf16(acc[1][2 * jj], ah1, bh[0], bh[1]);
                mma_bf16(acc[1][2 * jj], ah1, bl[0], bl[1]);
                mma_bf16(acc[1][2 * jj], al1, bh[0], bh[1]);
                mma_bf16(acc[0][2 * jj + 1], ah0, bh[2], bh[3]);
                mma_bf16(acc[0][2 * jj + 1], ah0, bl[2], bl[3]);
                mma_bf16(acc[0][2 * jj + 1], al0, bh[2], bh[3]);
                mma_bf16(acc[1][2 * jj + 1], ah1, bh[2], bh[3]);
                mma_bf16(acc[1][2 * jj + 1], ah1, bl[2], bl[3]);
                mma_bf16(acc[1][2 * jj + 1], al1, bh[2], bh[3]);
            }
        }
    }

    // ---- epilogue: scale by dis, store fp16 ----
    #pragma unroll
    for (int G = 0; G < 2; G++) {
        int r_lo = row0 + wid * 32 + G * 16 + g;
        int r_hi = r_lo + 8;
        float s_lo = (r_lo < NN) ? g_dis[r_lo] : 0.f;
        float s_hi = (r_hi < NN) ? g_dis[r_hi] : 0.f;
        #pragma unroll
        for (int j = 0; j < 8; j++) {
            int col = j * 8 + tig * 2;
            if (r_lo < NN)
                *(__half2*)&g_uh[(size_t)r_lo * 64 + col] =
                    __floats2half2_rn(acc[G][j][0] * s_lo, acc[G][j][1] * s_lo);
            if (r_hi < NN)
                *(__half2*)&g_uh[(size_t)r_hi * 64 + col] =
                    __floats2half2_rn(acc[G][j][2] * s_hi, acc[G][j][3] * s_hi);
        }
    }
}

// ---------------- aggregate + bias + relu (+ optional fused W3 dot) -----------
// h[d] = relu( dis[d] * ( sum_{e->d} u[src] + u[d] ) + b )
// FUSE_DOT: instead of writing h, compute u3[d] = dot(h[d], W3) * dis[d].
template <bool FUSE_DOT>
__global__ void agg_relu(const float* __restrict__ b, const float* __restrict__ W3) {
    int tid = threadIdx.x;
    int grp = tid >> 4, sub = tid & 15;
    int d = blockIdx.x * 16 + grp;

    const uint2* U = (const uint2*)g_uh;  // 4 halves per uint2, 16 per row
    uint2 raw = U[(size_t)d * 16 + sub];  // self-loop term
    float2 a0 = __half22float2(*(__half2*)&raw.x);
    float2 a1 = __half22float2(*(__half2*)&raw.y);
    float4 acc = make_float4(a0.x, a0.y, a1.x, a1.y);
    int e = g_off[d], end = g_off[d + 1];
    #pragma unroll 4
    for (; e < end; e++) {
        int s = g_csr[e];
        uint2 r2 = U[(size_t)s * 16 + sub];
        float2 v0 = __half22float2(*(__half2*)&r2.x);
        float2 v1 = __half22float2(*(__half2*)&r2.y);
        acc.x += v0.x; acc.y += v0.y; acc.z += v1.x; acc.w += v1.y;
    }
    float sc = g_dis[d];
    float4 bb = ((const float4*)b)[sub];
    float4 o;
    o.x = fmaxf(sc * acc.x + bb.x, 0.f);
    o.y = fmaxf(sc * acc.y + bb.y, 0.f);
    o.z = fmaxf(sc * acc.z + bb.z, 0.f);
    o.w = fmaxf(sc * acc.w + bb.w, 0.f);
    if (!FUSE_DOT) {
        ((float4*)g_h)[(size_t)d * 16 + sub] = o;
    } else {
        float4 w3 = ((const float4*)W3)[sub];
        float dot = o.x * w3.x + o.y * w3.y + o.z * w3.z + o.w * w3.w;
        #pragma unroll
        for (int off = 8; off; off >>= 1) dot += __shfl_xor_sync(0xffffffffu, dot, off);
        if (sub == 0) g_u3[d] = dot * sc;
    }
}

// ---------------- final: out = sigmoid(dis*(sum u3 + u3[d]) + b3) -------------
__global__ void final_k(const float* __restrict__ b3, float* __restrict__ out) {
    int d = blockIdx.x * blockDim.x + threadIdx.x;
    if (d < NN) {
        float s = g_u3[d];
        int e = g_off[d], end = g_off[d + 1];
        #pragma unroll 4
        for (; e < end; e++) s += g_u3[g_csr[e]];
        float z = g_dis[d] * s + b3[0];
        out[d] = 1.0f / (1.0f + expf(-z));
    }
}

// ---------------- launch -------------------------------------------------------
extern "C" void kernel_launch(void* const* d_in, const int* in_sizes, int n_in,
                              void* d_out, int out_size) {
    const float* x  = (const float*)d_in[0];
    const float* W1 = (const float*)d_in[1];
    const float* b1 = (const float*)d_in[2];
    const float* W2 = (const float*)d_in[3];
    const float* b2 = (const float*)d_in[4];
    const float* W3 = (const float*)d_in[5];
    const float* b3 = (const float*)d_in[6];
    const void*  ei = d_in[7];
    float* out = (float*)d_out;

    const int SMEM = 1024 + 65536 + 16384;  // pad + A(hi/lo) + B(hi/lo) = 82944
    cudaFuncSetAttribute(gemm_mma<2, false>, cudaFuncAttributeMaxDynamicSharedMemorySize, SMEM);
    cudaFuncSetAttribute(gemm_mma<1, true>,  cudaFuncAttributeMaxDynamicSharedMemorySize, SMEM);

    // graph structure (shared by all layers)
    detect_dtype<<<1, 256>>>((const int*)ei);
    zero_k<<<(NN + 255) / 256, 256>>>();
    count_k<<<(NE + 255) / 256, 256>>>(ei);
    scan1<<<SCAN_NBLK, 512>>>();
    scan2<<<1, 256>>>();
    scan3<<<(NN + 255) / 256, 256>>>();
    fill_k<<<(NE + 255) / 256, 256>>>(ei);

    const int NBLK = (NN + 255) / 256;  // 391

    // layer 1
    gemm_mma<2, false><<<NBLK, 256, SMEM>>>(x, W1);
    agg_relu<false><<<NN / 16, 256>>>(b1, nullptr);
    // layer 2 (+ fused layer-3 dot)
    gemm_mma<1, true><<<NBLK, 256, SMEM>>>(nullptr, W2);
    agg_relu<true><<<NN / 16, 256>>>(b2, W3);
    // final
    final_k<<<(NN + 255) / 256, 256>>>(b3, out);
}